// round 7
// baseline (speedup 1.0000x reference)
#include <cuda_runtime.h>
#include <cuda_bf16.h>
#include <math_constants.h>

// RWKV WKV scan. B=8, S=2048, H=2048.
// R6: single-pass chunked scan with decoupled lookback, NO SMEM tile.
// Phase 1 streams the k,v tile from DRAM (state-only scan from identity),
// phase 3 re-reads the same tile through L2 (concurrent working set ~38MB
// << 126MB L2). Removes 64 STS/LDS per thread and lifts occupancy 3->4
// blocks/SM. k,v cross DRAM exactly once.

#define S_   2048
#define H_   2048
#define B_   8
#define BH_  (B_ * H_)        // 16384 channels
#define CLEN 16               // steps per chunk
#define CC   (S_ / CLEN)      // 128 chunks
#define GCH  512              // channels per group
#define GROUPS (BH_ / GCH)    // 32
#define NT   128              // threads per block (4 channels each)
#define ROWQ (H_ / 4)         // 512 float4 per row

#define L2E 1.4426950408889634f

__device__ float4 g_aggm[GROUPS * CC * NT];
__device__ float4 g_aggn[GROUPS * CC * NT];
__device__ float4 g_aggd[GROUPS * CC * NT];
__device__ float4 g_incm[GROUPS * CC * NT];
__device__ float4 g_incn[GROUPS * CC * NT];
__device__ float4 g_incd[GROUPS * CC * NT];
__device__ int    g_status[GROUPS * CC];   // 0=none, 1=aggregate, 2=inclusive

__device__ __forceinline__ float ex2(float x) {
    float r;
    asm("ex2.approx.ftz.f32 %0, %1;" : "=f"(r) : "f"(x));
    return r;
}
__device__ __forceinline__ int ld_acquire(const int* p) {
    int v;
    asm volatile("ld.acquire.gpu.global.b32 %0, [%1];" : "=r"(v) : "l"(p));
    return v;
}
__device__ __forceinline__ void st_release(int* p, int v) {
    asm volatile("st.release.gpu.global.b32 [%0], %1;" :: "l"(p), "r"(v) : "memory");
}

__global__ void wkv_reset() {
    const int i = blockIdx.x * blockDim.x + threadIdx.x;
    if (i < GROUPS * CC) g_status[i] = 0;
}

__global__ void __launch_bounds__(NT, 4) wkv_main(
    const float* __restrict__ time_decay,
    const float* __restrict__ k,
    const float* __restrict__ time_first,
    const float* __restrict__ v,
    const float* __restrict__ m0,
    const float* __restrict__ n0,
    const float* __restrict__ d0,
    float* __restrict__ out)
{
    __shared__ int s_st;

    const int tid = threadIdx.x;
    const int g   = blockIdx.x & (GROUPS - 1);
    const int c   = blockIdx.x >> 5;           // GROUPS = 32
    const int ch0 = g * GCH + 4 * tid;
    const int h0  = ch0 & (H_ - 1);
    const int b   = ch0 >> 11;

    const float4 tdv = *(const float4*)(time_decay + h0);
    const float4 tfv = *(const float4*)(time_first + h0);
    float td[4] = { -__expf(tdv.x) * L2E, -__expf(tdv.y) * L2E,
                    -__expf(tdv.z) * L2E, -__expf(tdv.w) * L2E };
    float tf[4] = { tfv.x * L2E, tfv.y * L2E, tfv.z * L2E, tfv.w * L2E };

    const size_t baseq =
        ((size_t)b * S_ * H_ + (size_t)c * CLEN * H_ + (size_t)h0) >> 2;
    const float4* __restrict__ kp = (const float4*)k + baseq;
    const float4* __restrict__ vp = (const float4*)v + baseq;

    // ---------------- Phase 1: streaming state-only scan from identity -------
    float am[4], an[4], ad[4];
#pragma unroll
    for (int j = 0; j < 4; ++j) { am[j] = -CUDART_INF_F; an[j] = 0.f; ad[j] = 0.f; }

#pragma unroll
    for (int r = 0; r < CLEN; ++r) {
        const float4 k4 = kp[r * ROWQ];
        const float4 v4 = vp[r * ROWQ];
        const float* kf = (const float*)&k4;
        const float* vf = (const float*)&v4;
#pragma unroll
        for (int j = 0; j < 4; ++j) {
            const float a  = am[j] + td[j];
            const float d2 = fmaf(kf[j], -L2E, a);       // a - k*L2E
            const float es = ex2(-fabsf(d2));
            const float e1 = (d2 >= 0.f) ? 1.f : es;
            const float e2 = (d2 >= 0.f) ? es : 1.f;
            am[j] = fmaxf(a, kf[j] * L2E);
            an[j] = fmaf(e1, an[j], e2 * vf[j]);
            ad[j] = fmaf(e1, ad[j], e2);
        }
    }

    // ---------------- Phase 2: publish + lookback -> entry state -------------
    const int gi = g * CC + c;
    const int qi = gi * NT + tid;
    float exm[4], exn[4], exd[4];

    if (c == 0) {
        const float4 mm = *(const float4*)(m0 + ch0);
        const float4 nn = *(const float4*)(n0 + ch0);
        const float4 dd = *(const float4*)(d0 + ch0);
        exm[0] = mm.x * L2E; exm[1] = mm.y * L2E; exm[2] = mm.z * L2E; exm[3] = mm.w * L2E;
        exn[0] = nn.x; exn[1] = nn.y; exn[2] = nn.z; exn[3] = nn.w;
        exd[0] = dd.x; exd[1] = dd.y; exd[2] = dd.z; exd[3] = dd.w;
    } else {
        g_aggm[qi] = make_float4(am[0], am[1], am[2], am[3]);
        g_aggn[qi] = make_float4(an[0], an[1], an[2], an[3]);
        g_aggd[qi] = make_float4(ad[0], ad[1], ad[2], ad[3]);
        __syncthreads();
        if (tid == 0) st_release(&g_status[gi], 1);

        float sm[4], sn[4], sd[4];
#pragma unroll
        for (int j = 0; j < 4; ++j) { sm[j] = -CUDART_INF_F; sn[j] = 0.f; sd[j] = 0.f; }
        float slen = 0.f;
        int idx = gi - 1;

        for (;;) {
            if (tid == 0) {
                int s;
                while ((s = ld_acquire(&g_status[idx])) == 0) __nanosleep(40);
                s_st = s;
            }
            __syncthreads();
            const int s = s_st;
            __syncthreads();
            const int q2 = idx * NT + tid;
            if (s == 1) {
                const float4 A_m = g_aggm[q2];
                const float4 A_n = g_aggn[q2];
                const float4 A_d = g_aggd[q2];
                const float* Amf = (const float*)&A_m;
                const float* Anf = (const float*)&A_n;
                const float* Adf = (const float*)&A_d;
#pragma unroll
                for (int j = 0; j < 4; ++j) {
                    const float a  = fmaf(slen, td[j], Amf[j]);
                    const float mo = fmaxf(a, sm[j]);
                    const float e1 = ex2(a - mo);
                    const float e2 = ex2(sm[j] - mo);
                    sn[j] = fmaf(e1, Anf[j], e2 * sn[j]);
                    sd[j] = fmaf(e1, Adf[j], e2 * sd[j]);
                    sm[j] = mo;
                }
                slen += (float)CLEN;
                --idx;
            } else {
                const float4 E_m = g_incm[q2];
                const float4 E_n = g_incn[q2];
                const float4 E_d = g_incd[q2];
                const float* Emf = (const float*)&E_m;
                const float* Enf = (const float*)&E_n;
                const float* Edf = (const float*)&E_d;
#pragma unroll
                for (int j = 0; j < 4; ++j) {
                    const float a  = fmaf(slen, td[j], Emf[j]);
                    const float mo = fmaxf(a, sm[j]);
                    const float e1 = ex2(a - mo);
                    const float e2 = ex2(sm[j] - mo);
                    exn[j] = fmaf(e1, Enf[j], e2 * sn[j]);
                    exd[j] = fmaf(e1, Edf[j], e2 * sd[j]);
                    exm[j] = mo;
                }
                break;
            }
        }
    }

    // inclusive(c) = compose(exclusive, own aggregate over CLEN steps)
    {
        float im[4], in_[4], id_[4];
#pragma unroll
        for (int j = 0; j < 4; ++j) {
            const float a  = fmaf((float)CLEN, td[j], exm[j]);
            const float mo = fmaxf(a, am[j]);
            const float e1 = ex2(a - mo);
            const float e2 = ex2(am[j] - mo);
            in_[j] = fmaf(e1, exn[j], e2 * an[j]);
            id_[j] = fmaf(e1, exd[j], e2 * ad[j]);
            im[j]  = mo;
        }
        g_incm[qi] = make_float4(im[0], im[1], im[2], im[3]);
        g_incn[qi] = make_float4(in_[0], in_[1], in_[2], in_[3]);
        g_incd[qi] = make_float4(id_[0], id_[1], id_[2], id_[3]);
        __syncthreads();
        if (tid == 0) st_release(&g_status[gi], 2);
    }

    // ---------------- Phase 3: outputs (tile re-read hits L2) ----------------
    float m[4], num[4], den[4];
#pragma unroll
    for (int j = 0; j < 4; ++j) { m[j] = exm[j]; num[j] = exn[j]; den[j] = exd[j]; }

    float4* __restrict__ op = (float4*)out + baseq;

#pragma unroll
    for (int r = 0; r < CLEN; ++r) {
        const float4 k4 = kp[r * ROWQ];
        const float4 v4 = vp[r * ROWQ];
        const float* kf = (const float*)&k4;
        const float* vf = (const float*)&v4;
        float4 o4;
        float* of = (float*)&o4;
#pragma unroll
        for (int j = 0; j < 4; ++j) {
            const float vt = vf[j];

            // output branch: btf = k*L2E + tf
            const float btf = fmaf(kf[j], L2E, tf[j]);
            const float d1  = m[j] - btf;
            const float eo  = ex2(-fabsf(d1));
            const float e1o = (d1 >= 0.f) ? 1.f : eo;
            const float e2o = (d1 >= 0.f) ? eo : 1.f;
            const float on  = fmaf(e1o, num[j], e2o * vt);
            const float od  = fmaf(e1o, den[j], e2o);
            of[j] = __fdividef(on, od);

            // state branch
            const float a  = m[j] + td[j];
            const float d2 = fmaf(kf[j], -L2E, a);
            const float es = ex2(-fabsf(d2));
            const float e1 = (d2 >= 0.f) ? 1.f : es;
            const float e2 = (d2 >= 0.f) ? es : 1.f;
            m[j]   = fmaxf(a, kf[j] * L2E);
            num[j] = fmaf(e1, num[j], e2 * vt);
            den[j] = fmaf(e1, den[j], e2);
        }
        op[r * ROWQ] = o4;
    }

    if (c == CC - 1) {
        float* st = out + (size_t)B_ * S_ * H_;
        *(float4*)(st + ch0) = make_float4(m[0] * (1.f / L2E), m[1] * (1.f / L2E),
                                           m[2] * (1.f / L2E), m[3] * (1.f / L2E));
        *(float4*)(st + BH_ + ch0)     = make_float4(num[0], num[1], num[2], num[3]);
        *(float4*)(st + 2 * BH_ + ch0) = make_float4(den[0], den[1], den[2], den[3]);
    }
}

extern "C" void kernel_launch(void* const* d_in, const int* in_sizes, int n_in,
                              void* d_out, int out_size) {
    const float* time_decay = (const float*)d_in[0];
    const float* key        = (const float*)d_in[1];
    const float* time_first = (const float*)d_in[2];
    const float* value      = (const float*)d_in[3];
    const float* max_state  = (const float*)d_in[4];
    const float* num_state  = (const float*)d_in[5];
    const float* den_state  = (const float*)d_in[6];
    float* out = (float*)d_out;

    wkv_reset<<<(GROUPS * CC + 255) / 256, 256>>>();
    wkv_main<<<GROUPS * CC, NT>>>(time_decay, key, time_first, value,
                                  max_state, num_state, den_state, out);
}

// round 8
// speedup vs baseline: 1.1786x; 1.1786x over previous
#include <cuda_runtime.h>
#include <cuda_bf16.h>
#include <math_constants.h>

// RWKV WKV scan. B=8, S=2048, H=2048.
// R7: R5 structure (single-pass decoupled lookback + SMEM tile) with CLEN=8
// (32KB tile) and __launch_bounds__(128,5) -> 5 blocks/SM, 20 warps/SM.
// k,v cross DRAM exactly once; phase-3 replay comes from SMEM.

#define S_   2048
#define H_   2048
#define B_   8
#define BH_  (B_ * H_)        // 16384 channels
#define CLEN 8                // steps per chunk
#define CC   (S_ / CLEN)      // 256 chunks
#define GCH  512              // channels per group
#define GROUPS (BH_ / GCH)    // 32
#define NT   128              // threads per block (4 channels each)
#define ROWQ (H_ / 4)         // 512 float4 per row

#define L2E 1.4426950408889634f

__device__ float4 g_aggm[GROUPS * CC * NT];
__device__ float4 g_aggn[GROUPS * CC * NT];
__device__ float4 g_aggd[GROUPS * CC * NT];
__device__ float4 g_incm[GROUPS * CC * NT];
__device__ float4 g_incn[GROUPS * CC * NT];
__device__ float4 g_incd[GROUPS * CC * NT];
__device__ int    g_status[GROUPS * CC];   // 0=none, 1=aggregate, 2=inclusive

__device__ __forceinline__ float ex2(float x) {
    float r;
    asm("ex2.approx.ftz.f32 %0, %1;" : "=f"(r) : "f"(x));
    return r;
}
__device__ __forceinline__ int ld_acquire(const int* p) {
    int v;
    asm volatile("ld.acquire.gpu.global.b32 %0, [%1];" : "=r"(v) : "l"(p));
    return v;
}
__device__ __forceinline__ void st_release(int* p, int v) {
    asm volatile("st.release.gpu.global.b32 [%0], %1;" :: "l"(p), "r"(v) : "memory");
}

__global__ void wkv_reset() {
    const int i = blockIdx.x * blockDim.x + threadIdx.x;
    if (i < GROUPS * CC) g_status[i] = 0;
}

__global__ void __launch_bounds__(NT, 5) wkv_main(
    const float* __restrict__ time_decay,
    const float* __restrict__ k,
    const float* __restrict__ time_first,
    const float* __restrict__ v,
    const float* __restrict__ m0,
    const float* __restrict__ n0,
    const float* __restrict__ d0,
    float* __restrict__ out)
{
    extern __shared__ float4 sh[];
    float4* ks = sh;                 // [CLEN][NT], k pre-scaled by L2E
    float4* vs = sh + CLEN * NT;     // [CLEN][NT]
    __shared__ int s_st;

    const int tid = threadIdx.x;
    const int g   = blockIdx.x & (GROUPS - 1);
    const int c   = blockIdx.x >> 5;           // GROUPS = 32
    const int ch0 = g * GCH + 4 * tid;
    const int h0  = ch0 & (H_ - 1);
    const int b   = ch0 >> 11;

    const float4 tdv = *(const float4*)(time_decay + h0);
    float td[4] = { -__expf(tdv.x) * L2E, -__expf(tdv.y) * L2E,
                    -__expf(tdv.z) * L2E, -__expf(tdv.w) * L2E };

    const size_t baseq =
        ((size_t)b * S_ * H_ + (size_t)c * CLEN * H_ + (size_t)h0) >> 2;
    const float4* __restrict__ kp = (const float4*)k + baseq;
    const float4* __restrict__ vp = (const float4*)v + baseq;

    // ---------------- Phase 1: load tile + local scan from identity ----------
    float am[4], an[4], ad[4];
#pragma unroll
    for (int j = 0; j < 4; ++j) { am[j] = -CUDART_INF_F; an[j] = 0.f; ad[j] = 0.f; }

    float4 kb[4], vb[4];
#pragma unroll
    for (int r = 0; r < 4; ++r) { kb[r] = kp[r * ROWQ]; vb[r] = vp[r * ROWQ]; }

#pragma unroll
    for (int r = 0; r < CLEN; ++r) {
        const int slot = r & 3;
        float4 k4 = kb[slot];
        const float4 v4 = vb[slot];
        if (r + 4 < CLEN) { kb[slot] = kp[(r + 4) * ROWQ]; vb[slot] = vp[(r + 4) * ROWQ]; }
        k4.x *= L2E; k4.y *= L2E; k4.z *= L2E; k4.w *= L2E;
        ks[r * NT + tid] = k4;
        vs[r * NT + tid] = v4;
        const float* kf = (const float*)&k4;
        const float* vf = (const float*)&v4;
#pragma unroll
        for (int j = 0; j < 4; ++j) {
            const float a  = am[j] + td[j];
            const float d2 = a - kf[j];
            const float es = ex2(-fabsf(d2));
            const float e1 = (d2 >= 0.f) ? 1.f : es;
            const float e2 = (d2 >= 0.f) ? es : 1.f;
            am[j] = fmaxf(a, kf[j]);
            an[j] = fmaf(e1, an[j], e2 * vf[j]);
            ad[j] = fmaf(e1, ad[j], e2);
        }
    }

    // ---------------- Phase 2: publish + lookback -> entry state -------------
    const int gi = g * CC + c;
    const int qi = gi * NT + tid;
    float exm[4], exn[4], exd[4];

    if (c == 0) {
        const float4 mm = *(const float4*)(m0 + ch0);
        const float4 nn = *(const float4*)(n0 + ch0);
        const float4 dd = *(const float4*)(d0 + ch0);
        exm[0] = mm.x * L2E; exm[1] = mm.y * L2E; exm[2] = mm.z * L2E; exm[3] = mm.w * L2E;
        exn[0] = nn.x; exn[1] = nn.y; exn[2] = nn.z; exn[3] = nn.w;
        exd[0] = dd.x; exd[1] = dd.y; exd[2] = dd.z; exd[3] = dd.w;
    } else {
        g_aggm[qi] = make_float4(am[0], am[1], am[2], am[3]);
        g_aggn[qi] = make_float4(an[0], an[1], an[2], an[3]);
        g_aggd[qi] = make_float4(ad[0], ad[1], ad[2], ad[3]);
        __syncthreads();
        if (tid == 0) st_release(&g_status[gi], 1);

        float sm[4], sn[4], sd[4];
#pragma unroll
        for (int j = 0; j < 4; ++j) { sm[j] = -CUDART_INF_F; sn[j] = 0.f; sd[j] = 0.f; }
        float slen = 0.f;
        int idx = gi - 1;

        for (;;) {
            if (tid == 0) {
                int s;
                while ((s = ld_acquire(&g_status[idx])) == 0) __nanosleep(40);
                s_st = s;
            }
            __syncthreads();
            const int s = s_st;
            __syncthreads();
            const int q2 = idx * NT + tid;
            if (s == 1) {
                const float4 A_m = g_aggm[q2];
                const float4 A_n = g_aggn[q2];
                const float4 A_d = g_aggd[q2];
                const float* Amf = (const float*)&A_m;
                const float* Anf = (const float*)&A_n;
                const float* Adf = (const float*)&A_d;
#pragma unroll
                for (int j = 0; j < 4; ++j) {
                    const float a  = fmaf(slen, td[j], Amf[j]);
                    const float mo = fmaxf(a, sm[j]);
                    const float e1 = ex2(a - mo);
                    const float e2 = ex2(sm[j] - mo);
                    sn[j] = fmaf(e1, Anf[j], e2 * sn[j]);
                    sd[j] = fmaf(e1, Adf[j], e2 * sd[j]);
                    sm[j] = mo;
                }
                slen += (float)CLEN;
                --idx;
            } else {
                const float4 E_m = g_incm[q2];
                const float4 E_n = g_incn[q2];
                const float4 E_d = g_incd[q2];
                const float* Emf = (const float*)&E_m;
                const float* Enf = (const float*)&E_n;
                const float* Edf = (const float*)&E_d;
#pragma unroll
                for (int j = 0; j < 4; ++j) {
                    const float a  = fmaf(slen, td[j], Emf[j]);
                    const float mo = fmaxf(a, sm[j]);
                    const float e1 = ex2(a - mo);
                    const float e2 = ex2(sm[j] - mo);
                    exn[j] = fmaf(e1, Enf[j], e2 * sn[j]);
                    exd[j] = fmaf(e1, Edf[j], e2 * sd[j]);
                    exm[j] = mo;
                }
                break;
            }
        }
    }

    // inclusive(c) = compose(exclusive, own aggregate over CLEN steps)
    {
        float im[4], in_[4], id_[4];
#pragma unroll
        for (int j = 0; j < 4; ++j) {
            const float a  = fmaf((float)CLEN, td[j], exm[j]);
            const float mo = fmaxf(a, am[j]);
            const float e1 = ex2(a - mo);
            const float e2 = ex2(am[j] - mo);
            in_[j] = fmaf(e1, exn[j], e2 * an[j]);
            id_[j] = fmaf(e1, exd[j], e2 * ad[j]);
            im[j]  = mo;
        }
        g_incm[qi] = make_float4(im[0], im[1], im[2], im[3]);
        g_incn[qi] = make_float4(in_[0], in_[1], in_[2], in_[3]);
        g_incd[qi] = make_float4(id_[0], id_[1], id_[2], id_[3]);
        __syncthreads();
        if (tid == 0) st_release(&g_status[gi], 2);
    }

    // ---------------- Phase 3: outputs from exact entry state (SMEM replay) --
    const float4 tfv = *(const float4*)(time_first + h0);
    float tf[4] = { tfv.x * L2E, tfv.y * L2E, tfv.z * L2E, tfv.w * L2E };

    float m[4], num[4], den[4];
#pragma unroll
    for (int j = 0; j < 4; ++j) { m[j] = exm[j]; num[j] = exn[j]; den[j] = exd[j]; }

    float4* __restrict__ op = (float4*)out + baseq;

#pragma unroll
    for (int r = 0; r < CLEN; ++r) {
        const float4 k4 = ks[r * NT + tid];   // pre-scaled by L2E
        const float4 v4 = vs[r * NT + tid];
        const float* kf = (const float*)&k4;
        const float* vf = (const float*)&v4;
        float4 o4;
        float* of = (float*)&o4;
#pragma unroll
        for (int j = 0; j < 4; ++j) {
            const float kt = kf[j];
            const float vt = vf[j];

            // output branch
            const float btf = kt + tf[j];
            const float d1  = m[j] - btf;
            const float eo  = ex2(-fabsf(d1));
            const float e1o = (d1 >= 0.f) ? 1.f : eo;
            const float e2o = (d1 >= 0.f) ? eo : 1.f;
            const float on  = fmaf(e1o, num[j], e2o * vt);
            const float od  = fmaf(e1o, den[j], e2o);
            of[j] = __fdividef(on, od);

            // state branch
            const float a  = m[j] + td[j];
            const float d2 = a - kt;
            const float es = ex2(-fabsf(d2));
            const float e1 = (d2 >= 0.f) ? 1.f : es;
            const float e2 = (d2 >= 0.f) ? es : 1.f;
            m[j]   = fmaxf(a, kt);
            num[j] = fmaf(e1, num[j], e2 * vt);
            den[j] = fmaf(e1, den[j], e2);
        }
        op[r * ROWQ] = o4;
    }

    if (c == CC - 1) {
        float* st = out + (size_t)B_ * S_ * H_;
        *(float4*)(st + ch0) = make_float4(m[0] * (1.f / L2E), m[1] * (1.f / L2E),
                                           m[2] * (1.f / L2E), m[3] * (1.f / L2E));
        *(float4*)(st + BH_ + ch0)     = make_float4(num[0], num[1], num[2], num[3]);
        *(float4*)(st + 2 * BH_ + ch0) = make_float4(den[0], den[1], den[2], den[3]);
    }
}

extern "C" void kernel_launch(void* const* d_in, const int* in_sizes, int n_in,
                              void* d_out, int out_size) {
    const float* time_decay = (const float*)d_in[0];
    const float* key        = (const float*)d_in[1];
    const float* time_first = (const float*)d_in[2];
    const float* value      = (const float*)d_in[3];
    const float* max_state  = (const float*)d_in[4];
    const float* num_state  = (const float*)d_in[5];
    const float* den_state  = (const float*)d_in[6];
    float* out = (float*)d_out;

    const int smem = 2 * CLEN * NT * sizeof(float4);   // 32 KB
    cudaFuncSetAttribute(wkv_main, cudaFuncAttributeMaxDynamicSharedMemorySize, smem);

    wkv_reset<<<(GROUPS * CC + 255) / 256, 256>>>();
    wkv_main<<<GROUPS * CC, NT, smem>>>(time_decay, key, time_first, value,
                                        max_state, num_state, den_state, out);
}

// round 10
// speedup vs baseline: 1.6474x; 1.3978x over previous
#include <cuda_runtime.h>
#include <cuda_bf16.h>
#include <math_constants.h>

// RWKV WKV scan. B=8, S=2048, H=2048.
// R8: single-pass decoupled lookback (R5 structure), reshaped to CLEN=32 with
// GCH=256 channels/group and 2 channels/thread (float2). Tile stays 64KB ->
// 3 blocks/SM, but chunk count halves (CC=64): scratch traffic and lookback
// overhead halve. k,v cross DRAM exactly once; phase-3 replay from SMEM.

#define S_   2048
#define H_   2048
#define B_   8
#define BH_  (B_ * H_)        // 16384 channels
#define CLEN 32               // steps per chunk
#define CC   (S_ / CLEN)      // 64 chunks
#define GCH  256              // channels per group
#define GROUPS (BH_ / GCH)    // 64
#define NT   128              // threads per block (2 channels each)
#define ROW2 (H_ / 2)         // 1024 float2 per row
#define PF   8                // prefetch ring depth (rows)

#define L2E 1.4426950408889634f

__device__ float2 g_aggm[GROUPS * CC * NT];
__device__ float2 g_aggn[GROUPS * CC * NT];
__device__ float2 g_aggd[GROUPS * CC * NT];
__device__ float2 g_incm[GROUPS * CC * NT];
__device__ float2 g_incn[GROUPS * CC * NT];
__device__ float2 g_incd[GROUPS * CC * NT];
__device__ int    g_status[GROUPS * CC];   // 0=none, 1=aggregate, 2=inclusive

__device__ __forceinline__ float ex2(float x) {
    float r;
    asm("ex2.approx.ftz.f32 %0, %1;" : "=f"(r) : "f"(x));
    return r;
}
__device__ __forceinline__ int ld_acquire(const int* p) {
    int v;
    asm volatile("ld.acquire.gpu.global.b32 %0, [%1];" : "=r"(v) : "l"(p));
    return v;
}
__device__ __forceinline__ void st_release(int* p, int v) {
    asm volatile("st.release.gpu.global.b32 [%0], %1;" :: "l"(p), "r"(v) : "memory");
}

__global__ void wkv_reset() {
    const int i = blockIdx.x * blockDim.x + threadIdx.x;
    if (i < GROUPS * CC) g_status[i] = 0;
}

__global__ void __launch_bounds__(NT, 3) wkv_main(
    const float* __restrict__ time_decay,
    const float* __restrict__ k,
    const float* __restrict__ time_first,
    const float* __restrict__ v,
    const float* __restrict__ m0,
    const float* __restrict__ n0,
    const float* __restrict__ d0,
    float* __restrict__ out)
{
    extern __shared__ float2 sh[];
    float2* ks = sh;                 // [CLEN][NT], k pre-scaled by L2E
    float2* vs = sh + CLEN * NT;     // [CLEN][NT]
    __shared__ int s_st;

    const int tid = threadIdx.x;
    const int g   = blockIdx.x & (GROUPS - 1);
    const int c   = blockIdx.x >> 6;           // GROUPS = 64
    const int ch0 = g * GCH + 2 * tid;
    const int h0  = ch0 & (H_ - 1);
    const int b   = ch0 >> 11;

    const float2 tdv = *(const float2*)(time_decay + h0);
    float td[2] = { -__expf(tdv.x) * L2E, -__expf(tdv.y) * L2E };

    const size_t base2 =
        ((size_t)b * S_ * H_ + (size_t)c * CLEN * H_ + (size_t)h0) >> 1;
    const float2* __restrict__ kp = (const float2*)k + base2;
    const float2* __restrict__ vp = (const float2*)v + base2;

    // ---------------- Phase 1: load tile + local scan from identity ----------
    float am[2], an[2], ad[2];
#pragma unroll
    for (int j = 0; j < 2; ++j) { am[j] = -CUDART_INF_F; an[j] = 0.f; ad[j] = 0.f; }

    float2 kb[PF], vb[PF];
#pragma unroll
    for (int r = 0; r < PF; ++r) { kb[r] = kp[r * ROW2]; vb[r] = vp[r * ROW2]; }

#pragma unroll
    for (int r = 0; r < CLEN; ++r) {
        const int slot = r & (PF - 1);
        float2 k2 = kb[slot];
        const float2 v2 = vb[slot];
        if (r + PF < CLEN) { kb[slot] = kp[(r + PF) * ROW2]; vb[slot] = vp[(r + PF) * ROW2]; }
        k2.x *= L2E; k2.y *= L2E;
        ks[r * NT + tid] = k2;
        vs[r * NT + tid] = v2;
        const float* kf = (const float*)&k2;
        const float* vf = (const float*)&v2;
#pragma unroll
        for (int j = 0; j < 2; ++j) {
            const float a  = am[j] + td[j];
            const float d2 = a - kf[j];
            const float es = ex2(-fabsf(d2));
            const float e1 = (d2 >= 0.f) ? 1.f : es;
            const float e2 = (d2 >= 0.f) ? es : 1.f;
            am[j] = fmaxf(a, kf[j]);
            an[j] = fmaf(e1, an[j], e2 * vf[j]);
            ad[j] = fmaf(e1, ad[j], e2);
        }
    }

    // ---------------- Phase 2: publish + lookback -> entry state -------------
    const int gi = g * CC + c;
    const int qi = gi * NT + tid;
    float exm[2], exn[2], exd[2];

    if (c == 0) {
        const float2 mm = *(const float2*)(m0 + ch0);
        const float2 nn = *(const float2*)(n0 + ch0);
        const float2 dd = *(const float2*)(d0 + ch0);
        exm[0] = mm.x * L2E; exm[1] = mm.y * L2E;
        exn[0] = nn.x; exn[1] = nn.y;
        exd[0] = dd.x; exd[1] = dd.y;
    } else {
        g_aggm[qi] = make_float2(am[0], am[1]);
        g_aggn[qi] = make_float2(an[0], an[1]);
        g_aggd[qi] = make_float2(ad[0], ad[1]);
        __syncthreads();
        if (tid == 0) st_release(&g_status[gi], 1);

        float sm[2], sn[2], sd[2];
#pragma unroll
        for (int j = 0; j < 2; ++j) { sm[j] = -CUDART_INF_F; sn[j] = 0.f; sd[j] = 0.f; }
        float slen = 0.f;
        int idx = gi - 1;

        for (;;) {
            if (tid == 0) {
                int s;
                while ((s = ld_acquire(&g_status[idx])) == 0) __nanosleep(40);
                s_st = s;
            }
            __syncthreads();
            const int s = s_st;
            __syncthreads();
            const int q2 = idx * NT + tid;
            if (s == 1) {
                const float2 A_m = g_aggm[q2];
                const float2 A_n = g_aggn[q2];
                const float2 A_d = g_aggd[q2];
                const float* Amf = (const float*)&A_m;
                const float* Anf = (const float*)&A_n;
                const float* Adf = (const float*)&A_d;
#pragma unroll
                for (int j = 0; j < 2; ++j) {
                    const float a  = fmaf(slen, td[j], Amf[j]);
                    const float mo = fmaxf(a, sm[j]);
                    const float e1 = ex2(a - mo);
                    const float e2 = ex2(sm[j] - mo);
                    sn[j] = fmaf(e1, Anf[j], e2 * sn[j]);
                    sd[j] = fmaf(e1, Adf[j], e2 * sd[j]);
                    sm[j] = mo;
                }
                slen += (float)CLEN;
                --idx;
            } else {
                const float2 E_m = g_incm[q2];
                const float2 E_n = g_incn[q2];
                const float2 E_d = g_incd[q2];
                const float* Emf = (const float*)&E_m;
                const float* Enf = (const float*)&E_n;
                const float* Edf = (const float*)&E_d;
#pragma unroll
                for (int j = 0; j < 2; ++j) {
                    const float a  = fmaf(slen, td[j], Emf[j]);
                    const float mo = fmaxf(a, sm[j]);
                    const float e1 = ex2(a - mo);
                    const float e2 = ex2(sm[j] - mo);
                    exn[j] = fmaf(e1, Enf[j], e2 * sn[j]);
                    exd[j] = fmaf(e1, Edf[j], e2 * sd[j]);
                    exm[j] = mo;
                }
                break;
            }
        }
    }

    // inclusive(c) = compose(exclusive, own aggregate over CLEN steps)
    {
        float im[2], in_[2], id_[2];
#pragma unroll
        for (int j = 0; j < 2; ++j) {
            const float a  = fmaf((float)CLEN, td[j], exm[j]);
            const float mo = fmaxf(a, am[j]);
            const float e1 = ex2(a - mo);
            const float e2 = ex2(am[j] - mo);
            in_[j] = fmaf(e1, exn[j], e2 * an[j]);
            id_[j] = fmaf(e1, exd[j], e2 * ad[j]);
            im[j]  = mo;
        }
        g_incm[qi] = make_float2(im[0], im[1]);
        g_incn[qi] = make_float2(in_[0], in_[1]);
        g_incd[qi] = make_float2(id_[0], id_[1]);
        __syncthreads();
        if (tid == 0) st_release(&g_status[gi], 2);
    }

    // ---------------- Phase 3: outputs from exact entry state (SMEM replay) --
    const float2 tfv = *(const float2*)(time_first + h0);
    float tf[2] = { tfv.x * L2E, tfv.y * L2E };

    float m[2], num[2], den[2];
#pragma unroll
    for (int j = 0; j < 2; ++j) { m[j] = exm[j]; num[j] = exn[j]; den[j] = exd[j]; }

    float2* __restrict__ op = (float2*)out + base2;

#pragma unroll
    for (int r = 0; r < CLEN; ++r) {
        const float2 k2 = ks[r * NT + tid];   // pre-scaled by L2E
        const float2 v2 = vs[r * NT + tid];
        const float* kf = (const float*)&k2;
        const float* vf = (const float*)&v2;
        float2 o2;
        float* of = (float*)&o2;
#pragma unroll
        for (int j = 0; j < 2; ++j) {
            const float kt = kf[j];
            const float vt = vf[j];

            // output branch
            const float btf = kt + tf[j];
            const float d1  = m[j] - btf;
            const float eo  = ex2(-fabsf(d1));
            const float e1o = (d1 >= 0.f) ? 1.f : eo;
            const float e2o = (d1 >= 0.f) ? eo : 1.f;
            const float on  = fmaf(e1o, num[j], e2o * vt);
            const float od  = fmaf(e1o, den[j], e2o);
            of[j] = __fdividef(on, od);

            // state branch
            const float a  = m[j] + td[j];
            const float d2 = a - kt;
            const float es = ex2(-fabsf(d2));
            const float e1 = (d2 >= 0.f) ? 1.f : es;
            const float e2 = (d2 >= 0.f) ? es : 1.f;
            m[j]   = fmaxf(a, kt);
            num[j] = fmaf(e1, num[j], e2 * vt);
            den[j] = fmaf(e1, den[j], e2);
        }
        op[r * ROW2] = o2;
    }

    if (c == CC - 1) {
        float* st = out + (size_t)B_ * S_ * H_;
        *(float2*)(st + ch0)           = make_float2(m[0] * (1.f / L2E), m[1] * (1.f / L2E));
        *(float2*)(st + BH_ + ch0)     = make_float2(num[0], num[1]);
        *(float2*)(st + 2 * BH_ + ch0) = make_float2(den[0], den[1]);
    }
}

extern "C" void kernel_launch(void* const* d_in, const int* in_sizes, int n_in,
                              void* d_out, int out_size) {
    const float* time_decay = (const float*)d_in[0];
    const float* key        = (const float*)d_in[1];
    const float* time_first = (const float*)d_in[2];
    const float* value      = (const float*)d_in[3];
    const float* max_state  = (const float*)d_in[4];
    const float* num_state  = (const float*)d_in[5];
    const float* den_state  = (const float*)d_in[6];
    float* out = (float*)d_out;

    const int smem = 2 * CLEN * NT * sizeof(float2);   // 64 KB
    cudaFuncSetAttribute(wkv_main, cudaFuncAttributeMaxDynamicSharedMemorySize, smem);

    wkv_reset<<<(GROUPS * CC + 255) / 256, 256>>>();
    wkv_main<<<GROUPS * CC, NT, smem>>>(time_decay, key, time_first, value,
                                        max_state, num_state, den_state, out);
}